// round 13
// baseline (speedup 1.0000x reference)
#include <cuda_runtime.h>

// DWT1D bior3.5, J=3, fused. R11 = R7 compute core (packed 2-output loads,
// fma.rn.f32x2, conflict-free plain smem) + persistent CTAs with a dynamic
// row queue (592 CTAs = 4/SM x 148 SM, exactly one wave; atomic row counter
// reset by a tiny kernel captured in the same graph).
//
// lo[n] = sum_l s[2n-10+l]*h0[l]  (zero extension; odd-pad == zero extension)
// h1[i] = (i even ? -1 : +1) * h0[11-i]
// Output: [x0(=lo3) | hi1 | hi2 | hi3], rows concatenated per section.

#define N_IN   16384
#define O1     8197
#define O2     4104
#define O3     2057
#define NROWS  1024
#define NCTAS  592           // 4 * 148

#define SL1_F  8208      // valid [0,8197), zeros [8197,8208)
#define SL2_F  4116      // valid [0,4104), zeros [4104,4116)
#define SMEM_FLOATS (SL1_F + SL2_F)          // 12324 floats = 49296 B

#define OFF_X0  0
#define OFF_H1  ((size_t)NROWS * O3)
#define OFF_H2  (OFF_H1 + (size_t)NROWS * O1)
#define OFF_H3  (OFF_H2 + (size_t)NROWS * O2)

typedef unsigned long long u64;

__device__ int g_row_counter;

__device__ __forceinline__ u64 ffma2(u64 a, u64 b, u64 c) {
    u64 d;
    asm("fma.rn.f32x2 %0, %1, %2, %3;" : "=l"(d) : "l"(a), "l"(b), "l"(c));
    return d;
}
__device__ __forceinline__ u64 pack2(float x, float y) {
    u64 r;
    asm("mov.b64 %0, {%1, %2};" : "=l"(r) : "f"(x), "f"(y));
    return r;
}
__device__ __forceinline__ void unpack2(u64 a, float& x, float& y) {
    asm("mov.b64 {%0, %1}, %2;" : "=f"(x), "=f"(y) : "l"(a));
}
__device__ __forceinline__ float hsum2(u64 a) {
    float x, y;
    unpack2(a, x, y);
    return x + y;
}

// Alignment-checked pair store; predicate is warp-uniform (per-row base
// alignment, offsets are even).
__device__ __forceinline__ void store2(float* p, float a, float b) {
    if ((((size_t)p) & 7) == 0) *(float2*)p = make_float2(a, b);
    else { p[0] = a; p[1] = b; }
}

// One analysis level. Thread t computes outputs n = 2t, 2t+1 from
// src[4t-12 .. 4t+3], loaded as 4x 128-bit (8 natural even pairs vp[0..7]);
// lane stride 16B => fully packed L1 lines for both LDG and LDS.
// Fast path for 3 <= t <= tmax_fast; otherwise masked scalar (zero ext).
__device__ __forceinline__ void run_level(
    const float* __restrict__ src, int src_valid,
    int M, int G, int tmax_fast,
    const u64* __restrict__ ch0, const u64* __restrict__ ch1,
    float* __restrict__ lo_smem,     // nullable
    float* __restrict__ lo_gmem,     // nullable
    float* __restrict__ hi_gmem)
{
    for (int t = threadIdx.x; t < G; t += blockDim.x) {
        const int n0 = 2 * t;
        float lo0, lo1, hi0, hi1;

        if (t >= 3 && t <= tmax_fast) {
            const ulonglong2* s2 = (const ulonglong2*)src;
            u64 vp[8];
            #pragma unroll
            for (int q = 0; q < 4; q++) {
                ulonglong2 a = s2[t - 3 + q];
                vp[2 * q]     = a.x;
                vp[2 * q + 1] = a.y;
            }
            u64 a0 = 0ull, b0 = 0ull, a1 = 0ull, b1 = 0ull;
            #pragma unroll
            for (int m = 0; m < 6; m++) {
                a0 = ffma2(vp[1 + m], ch0[m], a0);
                b0 = ffma2(vp[1 + m], ch1[m], b0);
                a1 = ffma2(vp[2 + m], ch0[m], a1);
                b1 = ffma2(vp[2 + m], ch1[m], b1);
            }
            lo0 = hsum2(a0); hi0 = hsum2(b0);
            lo1 = hsum2(a1); hi1 = hsum2(b1);
        } else {
            float h0s[12], h1s[12];
            #pragma unroll
            for (int m = 0; m < 6; m++) {
                unpack2(ch0[m], h0s[2 * m], h0s[2 * m + 1]);
                unpack2(ch1[m], h1s[2 * m], h1s[2 * m + 1]);
            }
            float lv[2] = {0.f, 0.f}, hv[2] = {0.f, 0.f};
            #pragma unroll
            for (int j = 0; j < 2; j++) {
                const int n = n0 + j;
                #pragma unroll
                for (int l = 0; l < 12; l++) {
                    const int idx = 2 * n - 10 + l;
                    if (idx >= 0 && idx < src_valid) {
                        const float xv = src[idx];
                        lv[j] += xv * h0s[l];
                        hv[j] += xv * h1s[l];
                    }
                }
            }
            lo0 = lv[0]; hi0 = hv[0]; lo1 = lv[1]; hi1 = hv[1];
        }

        const bool ok1 = (n0 + 1 < M);
        if (lo_smem) {
            if (ok1) ((float2*)lo_smem)[t] = make_float2(lo0, lo1);
            else if (n0 < M) lo_smem[n0] = lo0;   // pads beyond M stay zero
        }
        if (ok1) {
            store2(hi_gmem + n0, hi0, hi1);
            if (lo_gmem) store2(lo_gmem + n0, lo0, lo1);
        } else if (n0 < M) {
            hi_gmem[n0] = hi0;
            if (lo_gmem) lo_gmem[n0] = lo0;
        }
    }
}

__global__ void reset_counter_kernel() {
    if (threadIdx.x == 0) g_row_counter = 0;
}

__global__ void __launch_bounds__(256, 4)
dwt1d_r11_kernel(const float* __restrict__ x,
                 const float* __restrict__ hac,
                 float* __restrict__ out)
{
    extern __shared__ float sm[];
    float* sl1 = sm;
    float* sl2 = sm + SL1_F;
    __shared__ int s_row;

    // Packed coefficient pairs: ch0[m]=(h0[2m],h0[2m+1]), ch1 likewise for h1.
    u64 ch0[6], ch1[6];
    {
        float h0s[12], h1s[12];
        #pragma unroll
        for (int i = 0; i < 12; i++) h0s[i] = __ldg(hac + i);
        #pragma unroll
        for (int i = 0; i < 12; i++)
            h1s[i] = ((i & 1) ? 1.0f : -1.0f) * h0s[11 - i];
        #pragma unroll
        for (int m = 0; m < 6; m++) {
            ch0[m] = pack2(h0s[2 * m], h0s[2 * m + 1]);
            ch1[m] = pack2(h1s[2 * m], h1s[2 * m + 1]);
        }
    }

    // Zero pads once; never overwritten (levels store only n < M into smem).
    if (threadIdx.x < 11)       sl1[O1 + threadIdx.x] = 0.f;        // 8197..8207
    else if (threadIdx.x < 23)  sl2[O2 + (threadIdx.x - 11)] = 0.f; // 4104..4115

    while (true) {
        // Dynamic row pull; sync also fences prior row's level-3 smem reads
        // before this row's level-1 smem writes.
        __syncthreads();
        if (threadIdx.x == 0) s_row = atomicAdd(&g_row_counter, 1);
        __syncthreads();
        const int row = s_row;
        if (row >= NROWS) break;

        const float* xr  = x + (size_t)row * N_IN;
        float* hi1 = out + OFF_H1 + (size_t)row * O1;
        float* hi2 = out + OFF_H2 + (size_t)row * O2;
        float* hi3 = out + OFF_H3 + (size_t)row * O3;
        float* x0  = out + OFF_X0 + (size_t)row * O3;

        // Level 1: gmem -> (sl1, hi1). G=4099; fast path t<=4095
        // (src[4t+3] <= 16383); t=4096..4098 do right zero-extension scalar.
        run_level(xr, N_IN, O1, 4099, 4095, ch0, ch1, sl1, nullptr, hi1);
        __syncthreads();
        // Level 2: sl1 -> (sl2, hi2). G=2052; max fast read 8207 < 8208.
        run_level(sl1, SL1_F, O2, 2052, 2051, ch0, ch1, sl2, nullptr, hi2);
        __syncthreads();
        // Level 3: sl2 -> (x0, hi3). G=1029; max fast read 4115 < 4116.
        run_level(sl2, SL2_F, O3, 1029, 1028, ch0, ch1, nullptr, x0, hi3);
    }
}

extern "C" void kernel_launch(void* const* d_in, const int* in_sizes, int n_in,
                              void* d_out, int out_size)
{
    int xi = 0, hi = 1;
    if (n_in >= 2 && in_sizes[0] == 12) { xi = 1; hi = 0; }

    const float* x   = (const float*)d_in[xi];
    const float* hac = (const float*)d_in[hi];
    float* out = (float*)d_out;

    const size_t smem_bytes = (size_t)SMEM_FLOATS * sizeof(float);   // 49296
    cudaFuncSetAttribute(dwt1d_r11_kernel,
                         cudaFuncAttributeMaxDynamicSharedMemorySize,
                         (int)smem_bytes);
    cudaFuncSetAttribute(dwt1d_r11_kernel,
                         cudaFuncAttributePreferredSharedMemoryCarveout, 100);

    reset_counter_kernel<<<1, 32>>>();
    dwt1d_r11_kernel<<<NCTAS, 256, smem_bytes>>>(x, hac, out);
}

// round 14
// speedup vs baseline: 1.0959x; 1.0959x over previous
#include <cuda_runtime.h>

// DWT1D bior3.5, J=3, fused. R13 = R7 (best known: packed 2-output loads,
// fma.rn.f32x2, conflict-free plain smem, static grid 1024, 4 CTAs/SM)
// + dual-group software pipelining inside each level: two groups spaced
// blockDim apart per loop iteration, loads for both issued before compute
// (2x memory-level parallelism per warp; lane stride stays 16B).
//
// lo[n] = sum_l s[2n-10+l]*h0[l]  (zero extension; odd-pad == zero extension)
// h1[i] = (i even ? -1 : +1) * h0[11-i]
// Output: [x0(=lo3) | hi1 | hi2 | hi3], rows concatenated per section.

#define N_IN   16384
#define O1     8197
#define O2     4104
#define O3     2057
#define NROWS  1024

#define SL1_F  8208      // valid [0,8197), zeros [8197,8208)
#define SL2_F  4116      // valid [0,4104), zeros [4104,4116)
#define SMEM_FLOATS (SL1_F + SL2_F)          // 12324 floats = 49296 B

#define OFF_X0  0
#define OFF_H1  ((size_t)NROWS * O3)
#define OFF_H2  (OFF_H1 + (size_t)NROWS * O1)
#define OFF_H3  (OFF_H2 + (size_t)NROWS * O2)

typedef unsigned long long u64;

__device__ __forceinline__ u64 ffma2(u64 a, u64 b, u64 c) {
    u64 d;
    asm("fma.rn.f32x2 %0, %1, %2, %3;" : "=l"(d) : "l"(a), "l"(b), "l"(c));
    return d;
}
__device__ __forceinline__ u64 pack2(float x, float y) {
    u64 r;
    asm("mov.b64 %0, {%1, %2};" : "=l"(r) : "f"(x), "f"(y));
    return r;
}
__device__ __forceinline__ void unpack2(u64 a, float& x, float& y) {
    asm("mov.b64 {%0, %1}, %2;" : "=f"(x), "=f"(y) : "l"(a));
}
__device__ __forceinline__ float hsum2(u64 a) {
    float x, y;
    unpack2(a, x, y);
    return x + y;
}

// 8 natural even pairs covering src[4t-12 .. 4t+3] (16B-lane-stride loads).
struct VP { u64 v[8]; };

__device__ __forceinline__ void load_vp(const ulonglong2* __restrict__ s2,
                                        int t, VP& w) {
    #pragma unroll
    for (int q = 0; q < 4; q++) {
        ulonglong2 a = s2[t - 3 + q];
        w.v[2 * q]     = a.x;
        w.v[2 * q + 1] = a.y;
    }
}

__device__ __forceinline__ void compute_vp(const VP& w,
                                           const u64* __restrict__ ch0,
                                           const u64* __restrict__ ch1,
                                           float& lo0, float& lo1,
                                           float& hi0, float& hi1) {
    u64 a0 = 0ull, b0 = 0ull, a1 = 0ull, b1 = 0ull;
    #pragma unroll
    for (int m = 0; m < 6; m++) {
        a0 = ffma2(w.v[1 + m], ch0[m], a0);
        b0 = ffma2(w.v[1 + m], ch1[m], b0);
        a1 = ffma2(w.v[2 + m], ch0[m], a1);
        b1 = ffma2(w.v[2 + m], ch1[m], b1);
    }
    lo0 = hsum2(a0); hi0 = hsum2(b0);
    lo1 = hsum2(a1); hi1 = hsum2(b1);
}

// Slow (edge) path for one group: zero extension via masked scalar taps.
__device__ __forceinline__ void compute_edge(const float* __restrict__ src,
                                             int src_valid, int t,
                                             const u64* __restrict__ ch0,
                                             const u64* __restrict__ ch1,
                                             float& lo0, float& lo1,
                                             float& hi0, float& hi1) {
    float h0s[12], h1s[12];
    #pragma unroll
    for (int m = 0; m < 6; m++) {
        unpack2(ch0[m], h0s[2 * m], h0s[2 * m + 1]);
        unpack2(ch1[m], h1s[2 * m], h1s[2 * m + 1]);
    }
    float lv[2] = {0.f, 0.f}, hv[2] = {0.f, 0.f};
    #pragma unroll
    for (int j = 0; j < 2; j++) {
        const int n = 2 * t + j;
        #pragma unroll
        for (int l = 0; l < 12; l++) {
            const int idx = 2 * n - 10 + l;
            if (idx >= 0 && idx < src_valid) {
                const float xv = src[idx];
                lv[j] += xv * h0s[l];
                hv[j] += xv * h1s[l];
            }
        }
    }
    lo0 = lv[0]; hi0 = hv[0]; lo1 = lv[1]; hi1 = hv[1];
}

__device__ __forceinline__ void emit_group(int t, int M,
                                           float lo0, float lo1,
                                           float hi0, float hi1,
                                           float* __restrict__ lo_smem,
                                           float* __restrict__ lo_gmem,
                                           float* __restrict__ hi_gmem) {
    const int n0 = 2 * t;
    const bool ok1 = (n0 + 1 < M);
    if (lo_smem) {
        if (ok1) ((float2*)lo_smem)[t] = make_float2(lo0, lo1);
        else if (n0 < M) lo_smem[n0] = lo0;
    }
    if (n0 < M) {
        hi_gmem[n0] = hi0;
        if (lo_gmem) lo_gmem[n0] = lo0;
    }
    if (ok1) {
        hi_gmem[n0 + 1] = hi1;
        if (lo_gmem) lo_gmem[n0 + 1] = lo1;
    }
}

// One analysis level, dual-group pipelined: iterations handle groups
// (t, t+blockDim); both groups' loads issue before any compute.
__device__ __forceinline__ void run_level(
    const float* __restrict__ src, int src_valid,
    int M, int G, int tmax_fast,
    const u64* __restrict__ ch0, const u64* __restrict__ ch1,
    float* __restrict__ lo_smem,     // nullable
    float* __restrict__ lo_gmem,     // nullable
    float* __restrict__ hi_gmem)
{
    const ulonglong2* s2 = (const ulonglong2*)src;
    const int bd = blockDim.x;

    for (int t0 = threadIdx.x; t0 < G; t0 += 2 * bd) {
        const int t1 = t0 + bd;
        const bool has1 = (t1 < G);
        const bool f0 = (t0 >= 3) && (t0 <= tmax_fast);
        const bool f1 = has1 && (t1 >= 3) && (t1 <= tmax_fast);

        VP w0, w1;
        if (f0) load_vp(s2, t0, w0);
        if (f1) load_vp(s2, t1, w1);

        float lo0, lo1, hi0, hi1;
        if (f0) compute_vp(w0, ch0, ch1, lo0, lo1, hi0, hi1);
        else    compute_edge(src, src_valid, t0, ch0, ch1, lo0, lo1, hi0, hi1);
        emit_group(t0, M, lo0, lo1, hi0, hi1, lo_smem, lo_gmem, hi_gmem);

        if (has1) {
            float lo2, lo3, hi2, hi3;
            if (f1) compute_vp(w1, ch0, ch1, lo2, lo3, hi2, hi3);
            else    compute_edge(src, src_valid, t1, ch0, ch1, lo2, lo3, hi2, hi3);
            emit_group(t1, M, lo2, lo3, hi2, hi3, lo_smem, lo_gmem, hi_gmem);
        }
    }
}

__global__ void __launch_bounds__(256, 4)
dwt1d_r13_kernel(const float* __restrict__ x,
                 const float* __restrict__ hac,
                 float* __restrict__ out)
{
    extern __shared__ float sm[];
    float* sl1 = sm;
    float* sl2 = sm + SL1_F;

    const int row = blockIdx.x;
    const float* xr = x + (size_t)row * N_IN;

    // Packed coefficient pairs: ch0[m]=(h0[2m],h0[2m+1]), ch1 likewise for h1.
    u64 ch0[6], ch1[6];
    {
        float h0s[12], h1s[12];
        #pragma unroll
        for (int i = 0; i < 12; i++) h0s[i] = __ldg(hac + i);
        #pragma unroll
        for (int i = 0; i < 12; i++)
            h1s[i] = ((i & 1) ? 1.0f : -1.0f) * h0s[11 - i];
        #pragma unroll
        for (int m = 0; m < 6; m++) {
            ch0[m] = pack2(h0s[2 * m], h0s[2 * m + 1]);
            ch1[m] = pack2(h1s[2 * m], h1s[2 * m + 1]);
        }
    }

    // Zero pads (zero-extension for the next level's fast path; never
    // overwritten: levels store only n < M into smem).
    if (threadIdx.x < 11)       sl1[O1 + threadIdx.x] = 0.f;        // 8197..8207
    else if (threadIdx.x < 23)  sl2[O2 + (threadIdx.x - 11)] = 0.f; // 4104..4115

    float* hi1 = out + OFF_H1 + (size_t)row * O1;
    float* hi2 = out + OFF_H2 + (size_t)row * O2;
    float* hi3 = out + OFF_H3 + (size_t)row * O3;
    float* x0  = out + OFF_X0 + (size_t)row * O3;

    // Level 1: gmem -> (sl1, hi1). G=4099; fast path t<=4095
    // (src[4t+3] <= 16383); t=4096..4098 do right zero-extension scalar.
    run_level(xr, N_IN, O1, 4099, 4095, ch0, ch1, sl1, nullptr, hi1);
    __syncthreads();
    // Level 2: sl1 -> (sl2, hi2). G=2052; max fast read 4*2051+3=8207 < 8208.
    run_level(sl1, SL1_F, O2, 2052, 2051, ch0, ch1, sl2, nullptr, hi2);
    __syncthreads();
    // Level 3: sl2 -> (x0, hi3). G=1029; max fast read 4*1028+3=4115 < 4116.
    run_level(sl2, SL2_F, O3, 1029, 1028, ch0, ch1, nullptr, x0, hi3);
}

extern "C" void kernel_launch(void* const* d_in, const int* in_sizes, int n_in,
                              void* d_out, int out_size)
{
    int xi = 0, hi = 1;
    if (n_in >= 2 && in_sizes[0] == 12) { xi = 1; hi = 0; }

    const float* x   = (const float*)d_in[xi];
    const float* hac = (const float*)d_in[hi];
    float* out = (float*)d_out;

    const size_t smem_bytes = (size_t)SMEM_FLOATS * sizeof(float);   // 49296
    cudaFuncSetAttribute(dwt1d_r13_kernel,
                         cudaFuncAttributeMaxDynamicSharedMemorySize,
                         (int)smem_bytes);
    cudaFuncSetAttribute(dwt1d_r13_kernel,
                         cudaFuncAttributePreferredSharedMemoryCarveout, 100);

    dwt1d_r13_kernel<<<NROWS, 256, smem_bytes>>>(x, hac, out);
}

// round 15
// speedup vs baseline: 1.1659x; 1.0639x over previous
#include <cuda_runtime.h>

// DWT1D bior3.5, J=3, fused. R14 = R7 core (packed 2-output loads,
// fma.rn.f32x2, conflict-free plain smem, grid 1024, 4 CTAs/SM) with each
// level fully unrolled at compile time (bd=256, trip counts 17/9/5):
//   head (mixed) / middle (pure fast path, no predicates, all addresses
//   [Rbase+imm]) / tail (3-5 threads, checked).
// Kills the ~30% ALU tax (loop control + per-group IMADs) measured in R13.
//
// lo[n] = sum_l s[2n-10+l]*h0[l]  (zero extension; odd-pad == zero extension)
// h1[i] = (i even ? -1 : +1) * h0[11-i]
// Output: [x0(=lo3) | hi1 | hi2 | hi3], rows concatenated per section.

#define N_IN   16384
#define O1     8197
#define O2     4104
#define O3     2057
#define NROWS  1024
#define BD     256

#define SL1_F  8208      // valid [0,8197), zeros [8197,8208)
#define SL2_F  4116      // valid [0,4104), zeros [4104,4116)
#define SMEM_FLOATS (SL1_F + SL2_F)          // 12324 floats = 49296 B

#define OFF_X0  0
#define OFF_H1  ((size_t)NROWS * O3)
#define OFF_H2  (OFF_H1 + (size_t)NROWS * O1)
#define OFF_H3  (OFF_H2 + (size_t)NROWS * O2)

typedef unsigned long long u64;

__device__ __forceinline__ u64 ffma2(u64 a, u64 b, u64 c) {
    u64 d;
    asm("fma.rn.f32x2 %0, %1, %2, %3;" : "=l"(d) : "l"(a), "l"(b), "l"(c));
    return d;
}
__device__ __forceinline__ u64 pack2(float x, float y) {
    u64 r;
    asm("mov.b64 %0, {%1, %2};" : "=l"(r) : "f"(x), "f"(y));
    return r;
}
__device__ __forceinline__ void unpack2(u64 a, float& x, float& y) {
    asm("mov.b64 {%0, %1}, %2;" : "=f"(x), "=f"(y) : "l"(a));
}
__device__ __forceinline__ float hsum2(u64 a) {
    float x, y;
    unpack2(a, x, y);
    return x + y;
}

// 8 natural even pairs covering src[4t-12 .. 4t+3] (16B lane stride).
struct VP { u64 v[8]; };

__device__ __forceinline__ void load_vp(const ulonglong2* __restrict__ s2,
                                        int t, VP& w) {
    #pragma unroll
    for (int q = 0; q < 4; q++) {
        ulonglong2 a = s2[t - 3 + q];
        w.v[2 * q]     = a.x;
        w.v[2 * q + 1] = a.y;
    }
}

__device__ __forceinline__ void compute_vp(const VP& w,
                                           const u64* __restrict__ ch0,
                                           const u64* __restrict__ ch1,
                                           float& lo0, float& lo1,
                                           float& hi0, float& hi1) {
    u64 a0 = 0ull, b0 = 0ull, a1 = 0ull, b1 = 0ull;
    #pragma unroll
    for (int m = 0; m < 6; m++) {
        a0 = ffma2(w.v[1 + m], ch0[m], a0);
        b0 = ffma2(w.v[1 + m], ch1[m], b0);
        a1 = ffma2(w.v[2 + m], ch0[m], a1);
        b1 = ffma2(w.v[2 + m], ch1[m], b1);
    }
    lo0 = hsum2(a0); hi0 = hsum2(b0);
    lo1 = hsum2(a1); hi1 = hsum2(b1);
}

// Edge path: zero extension via masked scalar taps.
__device__ __forceinline__ void compute_edge(const float* __restrict__ src,
                                             int src_valid, int t,
                                             const u64* __restrict__ ch0,
                                             const u64* __restrict__ ch1,
                                             float& lo0, float& lo1,
                                             float& hi0, float& hi1) {
    float h0s[12], h1s[12];
    #pragma unroll
    for (int m = 0; m < 6; m++) {
        unpack2(ch0[m], h0s[2 * m], h0s[2 * m + 1]);
        unpack2(ch1[m], h1s[2 * m], h1s[2 * m + 1]);
    }
    float lv[2] = {0.f, 0.f}, hv[2] = {0.f, 0.f};
    #pragma unroll
    for (int j = 0; j < 2; j++) {
        const int n = 2 * t + j;
        #pragma unroll
        for (int l = 0; l < 12; l++) {
            const int idx = 2 * n - 10 + l;
            if (idx >= 0 && idx < src_valid) {
                const float xv = src[idx];
                lv[j] += xv * h0s[l];
                hv[j] += xv * h1s[l];
            }
        }
    }
    lo0 = lv[0]; hi0 = hv[0]; lo1 = lv[1]; hi1 = hv[1];
}

// Unconditional emit (middle/head groups: provably n0+1 < M).
__device__ __forceinline__ void emit_full(int t,
                                          float lo0, float lo1,
                                          float hi0, float hi1,
                                          float* __restrict__ lo_smem,
                                          float* __restrict__ lo_gmem,
                                          float* __restrict__ hi_gmem) {
    const int n0 = 2 * t;
    if (lo_smem) ((float2*)lo_smem)[t] = make_float2(lo0, lo1);
    hi_gmem[n0]     = hi0;
    hi_gmem[n0 + 1] = hi1;
    if (lo_gmem) { lo_gmem[n0] = lo0; lo_gmem[n0 + 1] = lo1; }
}

// One level, fully unrolled. G = total groups, NMID = # provably-fast middle
// iterations (i=1..NMID), TAIL_FAST = tail groups may use the vector path
// (their loads stay inside src_valid incl. zero pads).
template<int M, int G, int NMID, bool TAIL_FAST>
__device__ __forceinline__ void run_level(
    const float* __restrict__ src, int src_valid,
    const u64* __restrict__ ch0, const u64* __restrict__ ch1,
    float* __restrict__ lo_smem,     // nullable (compile-time)
    float* __restrict__ lo_gmem,     // nullable (compile-time)
    float* __restrict__ hi_gmem)
{
    const ulonglong2* s2 = (const ulonglong2*)src;
    const int tid = threadIdx.x;

    // head (i = 0): only threads t<3 diverge into the edge path.
    {
        const int t = tid;
        float lo0, lo1, hi0, hi1;
        if (t >= 3) {
            VP w; load_vp(s2, t, w);
            compute_vp(w, ch0, ch1, lo0, lo1, hi0, hi1);
        } else {
            compute_edge(src, src_valid, t, ch0, ch1, lo0, lo1, hi0, hi1);
        }
        emit_full(t, lo0, lo1, hi0, hi1, lo_smem, lo_gmem, hi_gmem);
    }

    // middle: pure fast path, no predicates, immediate-offset addresses.
    #pragma unroll
    for (int i = 1; i <= NMID; i++) {
        const int t = tid + i * BD;
        VP w; load_vp(s2, t, w);
        float lo0, lo1, hi0, hi1;
        compute_vp(w, ch0, ch1, lo0, lo1, hi0, hi1);
        emit_full(t, lo0, lo1, hi0, hi1, lo_smem, lo_gmem, hi_gmem);
    }

    // tail: few threads, checked emit.
    {
        const int t = tid + (NMID + 1) * BD;
        if (t < G) {
            float lo0, lo1, hi0, hi1;
            if (TAIL_FAST) {
                VP w; load_vp(s2, t, w);
                compute_vp(w, ch0, ch1, lo0, lo1, hi0, hi1);
            } else {
                compute_edge(src, src_valid, t, ch0, ch1, lo0, lo1, hi0, hi1);
            }
            const int n0 = 2 * t;
            const bool ok1 = (n0 + 1 < M);
            if (lo_smem) {
                if (ok1) ((float2*)lo_smem)[t] = make_float2(lo0, lo1);
                else     lo_smem[n0] = lo0;     // pads beyond M stay zero
            }
            hi_gmem[n0] = hi0;
            if (lo_gmem) lo_gmem[n0] = lo0;
            if (ok1) {
                hi_gmem[n0 + 1] = hi1;
                if (lo_gmem) lo_gmem[n0 + 1] = lo1;
            }
        }
    }
}

__global__ void __launch_bounds__(BD, 4)
dwt1d_r14_kernel(const float* __restrict__ x,
                 const float* __restrict__ hac,
                 float* __restrict__ out)
{
    extern __shared__ float sm[];
    float* sl1 = sm;
    float* sl2 = sm + SL1_F;

    const int row = blockIdx.x;
    const float* xr = x + (size_t)row * N_IN;

    // Packed coefficient pairs: ch0[m]=(h0[2m],h0[2m+1]), ch1 likewise for h1.
    u64 ch0[6], ch1[6];
    {
        float h0s[12], h1s[12];
        #pragma unroll
        for (int i = 0; i < 12; i++) h0s[i] = __ldg(hac + i);
        #pragma unroll
        for (int i = 0; i < 12; i++)
            h1s[i] = ((i & 1) ? 1.0f : -1.0f) * h0s[11 - i];
        #pragma unroll
        for (int m = 0; m < 6; m++) {
            ch0[m] = pack2(h0s[2 * m], h0s[2 * m + 1]);
            ch1[m] = pack2(h1s[2 * m], h1s[2 * m + 1]);
        }
    }

    // Zero pads (zero-extension for the next level's fast path; never
    // overwritten: levels store only n < M into smem).
    if (threadIdx.x < 11)       sl1[O1 + threadIdx.x] = 0.f;        // 8197..8207
    else if (threadIdx.x < 23)  sl2[O2 + (threadIdx.x - 11)] = 0.f; // 4104..4115

    float* hi1 = out + OFF_H1 + (size_t)row * O1;
    float* hi2 = out + OFF_H2 + (size_t)row * O2;
    float* hi3 = out + OFF_H3 + (size_t)row * O3;
    float* x0  = out + OFF_X0 + (size_t)row * O3;

    // Level 1: gmem -> (sl1, hi1). G=4099, middle i=1..15 (t<=4095: max read
    // 4*4095+3 = 16383 ✓); tail t=4096..4098 is the right zero-extension edge.
    run_level<O1, 4099, 15, false>(xr, N_IN, ch0, ch1, sl1, nullptr, hi1);
    __syncthreads();
    // Level 2: sl1 -> (sl2, hi2). G=2052, middle i=1..7 (t<=2047); tail
    // t=2048..2051 fast (max read 4*2051+3 = 8207 < 8208).
    run_level<O2, 2052, 7, true>(sl1, SL1_F, ch0, ch1, sl2, nullptr, hi2);
    __syncthreads();
    // Level 3: sl2 -> (x0, hi3). G=1029, middle i=1..3 (t<=1023); tail
    // t=1024..1028 fast (max read 4*1028+3 = 4115 < 4116).
    run_level<O3, 1029, 3, true>(sl2, SL2_F, ch0, ch1, nullptr, x0, hi3);
}

extern "C" void kernel_launch(void* const* d_in, const int* in_sizes, int n_in,
                              void* d_out, int out_size)
{
    int xi = 0, hi = 1;
    if (n_in >= 2 && in_sizes[0] == 12) { xi = 1; hi = 0; }

    const float* x   = (const float*)d_in[xi];
    const float* hac = (const float*)d_in[hi];
    float* out = (float*)d_out;

    const size_t smem_bytes = (size_t)SMEM_FLOATS * sizeof(float);   // 49296
    cudaFuncSetAttribute(dwt1d_r14_kernel,
                         cudaFuncAttributeMaxDynamicSharedMemorySize,
                         (int)smem_bytes);
    cudaFuncSetAttribute(dwt1d_r14_kernel,
                         cudaFuncAttributePreferredSharedMemoryCarveout, 100);

    dwt1d_r14_kernel<<<NROWS, BD, smem_bytes>>>(x, hac, out);
}